// round 3
// baseline (speedup 1.0000x reference)
#include <cuda_runtime.h>
#include <math.h>
#include <stdint.h>

#define NB 2
#define NS 2048
#define NH 8
#define ND 64
#define HD 512
#define NM (NB*NS)   // 4096

// Scratch (allocation-free rule: static device globals)
__device__ float g_qp[NB*NS*HD];
__device__ float g_kp[NB*NS*HD];
__device__ float g_vp[NB*NS*HD];
__device__ float g_ctx[NB*NS*HD];
__device__ int   g_mask_mode;   // 0=int8/bool bytes, 1=int32, 2=float32

// Classify mask dtype from its first 16 elements. Values are 0/1.
// int32 0/1 words reinterpreted as float are 0.0f or denormal 1.4e-45 (not 1.0f);
// float32 0.0/1.0 words as int are 0 or 0x3F800000 (not 0/1);
// bool bytes as int32 words are random byte patterns (prob ~2^-24/word of looking like 0/1).
__global__ void detect_mask_kernel(const void* mask) {
    const int*   mi = (const int*)mask;
    const float* mf = (const float*)mask;
    bool i32 = true, f32 = true;
    for (int i = 0; i < 16; i++) {
        int v = mi[i];
        if (v != 0 && v != 1) i32 = false;
        float f = mf[i];
        if (!(f == 0.0f || f == 1.0f)) f32 = false;
    }
    g_mask_mode = i32 ? 1 : (f32 ? 2 : 0);
}

// FFMA-based exp (avoids MUFU bottleneck: rt_SMSP=8 on sm_103a).
// exp(x) = 2^(x*log2e); |f| <= 0.5 Taylor, rel err ~2e-6.
__device__ __forceinline__ float fexp(float x) {
    float z = x * 1.4426950408889634f;
    z = fmaxf(z, -120.0f);
    float fl = rintf(z);
    float f = z - fl;
    float p = 1.3333558e-3f;
    p = fmaf(p, f, 9.6181291e-3f);
    p = fmaf(p, f, 5.5504109e-2f);
    p = fmaf(p, f, 2.4022651e-1f);
    p = fmaf(p, f, 6.9314718e-1f);
    p = fmaf(p, f, 1.0f);
    int e = (int)fl;
    float r = __int_as_float((e + 127) << 23);
    return p * r;
}

// C[M,512] = A[M,512] @ W[512,512] + bias[512]
__global__ __launch_bounds__(256) void gemm_bias(const float* __restrict__ A,
                                                 const float* __restrict__ W,
                                                 const float* __restrict__ bias,
                                                 float* __restrict__ C) {
    __shared__ float AsT[16][68];
    __shared__ float Bs[16][68];
    const int K = 512, N = 512;
    int t = threadIdx.x;
    int tx = t & 15, ty = t >> 4;
    int m0 = blockIdx.y * 64, n0 = blockIdx.x * 64;
    float acc[4][4] = {};

    for (int k0 = 0; k0 < K; k0 += 16) {
        {
            int r  = t >> 2;           // 0..63
            int kg = (t & 3) << 2;     // 0,4,8,12
            float4 a = *(const float4*)&A[(size_t)(m0 + r) * K + k0 + kg];
            AsT[kg + 0][r] = a.x; AsT[kg + 1][r] = a.y;
            AsT[kg + 2][r] = a.z; AsT[kg + 3][r] = a.w;
            int kr = t >> 4;           // 0..15
            int cg = (t & 15) << 2;    // 0..60
            *(float4*)&Bs[kr][cg] = *(const float4*)&W[(size_t)(k0 + kr) * N + n0 + cg];
        }
        __syncthreads();
        #pragma unroll
        for (int kk = 0; kk < 16; kk++) {
            float4 a4 = *(const float4*)&AsT[kk][ty * 4];
            float4 b4 = *(const float4*)&Bs[kk][tx * 4];
            float av[4] = {a4.x, a4.y, a4.z, a4.w};
            float bv[4] = {b4.x, b4.y, b4.z, b4.w};
            #pragma unroll
            for (int i = 0; i < 4; i++)
                #pragma unroll
                for (int j = 0; j < 4; j++)
                    acc[i][j] = fmaf(av[i], bv[j], acc[i][j]);
        }
        __syncthreads();
    }
    float4 bb = *(const float4*)&bias[n0 + tx * 4];
    #pragma unroll
    for (int i = 0; i < 4; i++) {
        float4 o;
        o.x = acc[i][0] + bb.x;
        o.y = acc[i][1] + bb.y;
        o.z = acc[i][2] + bb.z;
        o.w = acc[i][3] + bb.w;
        *(float4*)&C[(size_t)(m0 + ty * 4 + i) * N + n0 + tx * 4] = o;
    }
}

// Flash attention: per block (q-tile of 64, head, batch), BN=64 k-tiles.
__global__ __launch_bounds__(256) void attn_kernel(const float* __restrict__ Qp,
                                                   const float* __restrict__ Kp,
                                                   const float* __restrict__ Vp,
                                                   const float* __restrict__ bias,
                                                   const void* __restrict__ mask,
                                                   float* __restrict__ ctx) {
    extern __shared__ float sm[];
    float (*QsT)[68] = (float(*)[68])(sm);
    float (*KsT)[68] = (float(*)[68])(sm + 64 * 68);
    float (*Vs)[68]  = (float(*)[68])(sm + 2 * 64 * 68);
    float (*PsT)[68] = (float(*)[68])(sm + 3 * 64 * 68);

    int t = threadIdx.x;
    int tx = t & 15, ty = t >> 4;
    int q0 = blockIdx.x * 64;
    int h = blockIdx.y, b = blockIdx.z;
    int mode = g_mask_mode;

    const float* Qbase = Qp + (size_t)b * NS * HD + h * ND;
    const float* Kbase = Kp + (size_t)b * NS * HD + h * ND;
    const float* Vbase = Vp + (size_t)b * NS * HD + h * ND;
    const float* Bbase = bias + (size_t)h * NS * NS;

    // Load Q tile (transposed into smem), pre-scaled by 1/sqrt(d)=0.125
    #pragma unroll
    for (int i = 0; i < 4; i++) {
        int idx = i * 256 + t;
        int r  = idx >> 4;          // 0..63
        int kg = (idx & 15) << 2;   // 0..60
        float4 qv = *(const float4*)&Qbase[(size_t)(q0 + r) * HD + kg];
        QsT[kg + 0][r] = qv.x * 0.125f;
        QsT[kg + 1][r] = qv.y * 0.125f;
        QsT[kg + 2][r] = qv.z * 0.125f;
        QsT[kg + 3][r] = qv.w * 0.125f;
    }

    float m[4], l[4], o[4][4];
    #pragma unroll
    for (int i = 0; i < 4; i++) {
        m[i] = -1e30f; l[i] = 0.0f;
        #pragma unroll
        for (int j = 0; j < 4; j++) o[i][j] = 0.0f;
    }

    for (int k0 = 0; k0 < NS; k0 += 64) {
        __syncthreads();   // prev GEMM2 readers done before overwriting K/V
        #pragma unroll
        for (int i = 0; i < 4; i++) {
            int idx = i * 256 + t;
            int c  = idx >> 4;
            int kg = (idx & 15) << 2;
            float4 kv = *(const float4*)&Kbase[(size_t)(k0 + c) * HD + kg];
            KsT[kg + 0][c] = kv.x; KsT[kg + 1][c] = kv.y;
            KsT[kg + 2][c] = kv.z; KsT[kg + 3][c] = kv.w;
            float4 vv = *(const float4*)&Vbase[(size_t)(k0 + c) * HD + kg];
            *(float4*)&Vs[c][kg] = vv;
        }
        __syncthreads();

        // GEMM1: S = Q @ K^T   (64x64x64)
        float s[4][4] = {};
        #pragma unroll 16
        for (int kk = 0; kk < 64; kk++) {
            float4 q4 = *(const float4*)&QsT[kk][ty * 4];
            float4 k4 = *(const float4*)&KsT[kk][tx * 4];
            float qa[4] = {q4.x, q4.y, q4.z, q4.w};
            float ka[4] = {k4.x, k4.y, k4.z, k4.w};
            #pragma unroll
            for (int i = 0; i < 4; i++)
                #pragma unroll
                for (int j = 0; j < 4; j++)
                    s[i][j] = fmaf(qa[i], ka[j], s[i][j]);
        }

        // bias + mask (mask dtype resolved at runtime: bytes / int32 / float32)
        #pragma unroll
        for (int i = 0; i < 4; i++) {
            int rq = q0 + ty * 4 + i;
            size_t off = (size_t)rq * NS + k0 + tx * 4;
            float4 b4 = *(const float4*)&Bbase[off];
            unsigned k0f, k1f, k2f, k3f;
            if (mode == 1) {
                int4 mm = *(const int4*)&((const int*)mask)[off];
                k0f = mm.x != 0; k1f = mm.y != 0; k2f = mm.z != 0; k3f = mm.w != 0;
            } else if (mode == 2) {
                float4 mm = *(const float4*)&((const float*)mask)[off];
                k0f = mm.x != 0.0f; k1f = mm.y != 0.0f; k2f = mm.z != 0.0f; k3f = mm.w != 0.0f;
            } else {
                unsigned int m4 = *(const unsigned int*)&((const unsigned char*)mask)[off];
                k0f = m4 & 0x000000FFu; k1f = m4 & 0x0000FF00u;
                k2f = m4 & 0x00FF0000u; k3f = m4 & 0xFF000000u;
            }
            s[i][0] = k0f ? s[i][0] + b4.x : -1e30f;
            s[i][1] = k1f ? s[i][1] + b4.y : -1e30f;
            s[i][2] = k2f ? s[i][2] + b4.z : -1e30f;
            s[i][3] = k3f ? s[i][3] + b4.w : -1e30f;
        }

        // online softmax (rows spread over 16 consecutive lanes: tx)
        #pragma unroll
        for (int i = 0; i < 4; i++) {
            float tm = fmaxf(fmaxf(s[i][0], s[i][1]), fmaxf(s[i][2], s[i][3]));
            #pragma unroll
            for (int w = 1; w < 16; w <<= 1)
                tm = fmaxf(tm, __shfl_xor_sync(0xFFFFFFFFu, tm, w));
            float mn = fmaxf(m[i], tm);
            float sc = fexp(m[i] - mn);
            m[i] = mn;
            l[i] *= sc;
            float rs = 0.0f;
            #pragma unroll
            for (int j = 0; j < 4; j++) {
                float p = fexp(s[i][j] - mn);
                s[i][j] = p;
                rs += p;
            }
            l[i] += rs;
            #pragma unroll
            for (int j = 0; j < 4; j++) o[i][j] *= sc;
        }

        // write P transposed: PsT[kc][r]
        #pragma unroll
        for (int j = 0; j < 4; j++) {
            float4 pv = make_float4(s[0][j], s[1][j], s[2][j], s[3][j]);
            *(float4*)&PsT[tx * 4 + j][ty * 4] = pv;
        }
        __syncthreads();

        // GEMM2: O += P @ V   (64x64x64)
        #pragma unroll 16
        for (int kk = 0; kk < 64; kk++) {
            float4 p4 = *(const float4*)&PsT[kk][ty * 4];
            float4 v4 = *(const float4*)&Vs[kk][tx * 4];
            float pa[4] = {p4.x, p4.y, p4.z, p4.w};
            float va[4] = {v4.x, v4.y, v4.z, v4.w};
            #pragma unroll
            for (int i = 0; i < 4; i++)
                #pragma unroll
                for (int j = 0; j < 4; j++)
                    o[i][j] = fmaf(pa[i], va[j], o[i][j]);
        }
    }

    // finalize: full row-sum l, divide, write ctx[b, q, h*64 + d]
    #pragma unroll
    for (int i = 0; i < 4; i++) {
        float lf = l[i];
        #pragma unroll
        for (int w = 1; w < 16; w <<= 1)
            lf += __shfl_xor_sync(0xFFFFFFFFu, lf, w);
        float inv = 1.0f / lf;
        float4 ov = make_float4(o[i][0] * inv, o[i][1] * inv, o[i][2] * inv, o[i][3] * inv);
        *(float4*)&ctx[(size_t)(b * NS + q0 + ty * 4 + i) * HD + h * ND + tx * 4] = ov;
    }
}

extern "C" void kernel_launch(void* const* d_in, const int* in_sizes, int n_in,
                              void* d_out, int out_size) {
    const float* k    = (const float*)d_in[0];
    const float* v    = (const float*)d_in[1];
    const float* q    = (const float*)d_in[2];
    const void*  mask = d_in[3];
    const float* sbias = (const float*)d_in[4];
    const float* Wq = (const float*)d_in[5];
    const float* bq = (const float*)d_in[6];
    const float* Wk = (const float*)d_in[7];
    const float* bk = (const float*)d_in[8];
    const float* Wv = (const float*)d_in[9];
    const float* bv = (const float*)d_in[10];
    const float* Wo = (const float*)d_in[11];
    const float* bo = (const float*)d_in[12];
    float* out = (float*)d_out;

    float *qp, *kp, *vp, *ctx;
    cudaGetSymbolAddress((void**)&qp,  g_qp);
    cudaGetSymbolAddress((void**)&kp,  g_kp);
    cudaGetSymbolAddress((void**)&vp,  g_vp);
    cudaGetSymbolAddress((void**)&ctx, g_ctx);

    cudaFuncSetAttribute(attn_kernel, cudaFuncAttributeMaxDynamicSharedMemorySize, 4 * 64 * 68 * 4);

    detect_mask_kernel<<<1, 1>>>(mask);

    dim3 gb(8, 64);   // N/64, M/64
    gemm_bias<<<gb, 256>>>(q, Wq, bq, qp);
    gemm_bias<<<gb, 256>>>(k, Wk, bk, kp);
    gemm_bias<<<gb, 256>>>(v, Wv, bv, vp);

    dim3 ga(NS / 64, NH, NB);
    attn_kernel<<<ga, 256, 4 * 64 * 68 * 4>>>(qp, kp, vp, sbias, mask, ctx);

    gemm_bias<<<gb, 256>>>(ctx, Wo, bo, out);
}

// round 4
// speedup vs baseline: 2.1223x; 2.1223x over previous
#include <cuda_runtime.h>
#include <math.h>
#include <stdint.h>

#define NB 2
#define NS 2048
#define NH 8
#define ND 64
#define HD 512

__device__ float g_qp[NB*NS*HD];
__device__ float g_kp[NB*NS*HD];
__device__ float g_vp[NB*NS*HD];
__device__ float g_ctx[NB*NS*HD];
__device__ int   g_mask_mode;   // 0=bytes, 1=int32, 2=float32

__global__ void detect_mask_kernel(const void* mask) {
    const int*   mi = (const int*)mask;
    const float* mf = (const float*)mask;
    bool i32 = true, f32 = true;
    for (int i = 0; i < 16; i++) {
        int v = mi[i];
        if (v != 0 && v != 1) i32 = false;
        float f = mf[i];
        if (!(f == 0.0f || f == 1.0f)) f32 = false;
    }
    g_mask_mode = i32 ? 1 : (f32 ? 2 : 0);
}

// FFMA-based exp (avoid MUFU rt=8)
__device__ __forceinline__ float fexp(float x) {
    float z = x * 1.4426950408889634f;
    z = fmaxf(z, -120.0f);
    float fl = rintf(z);
    float f = z - fl;
    float p = 1.3333558e-3f;
    p = fmaf(p, f, 9.6181291e-3f);
    p = fmaf(p, f, 5.5504109e-2f);
    p = fmaf(p, f, 2.4022651e-1f);
    p = fmaf(p, f, 6.9314718e-1f);
    p = fmaf(p, f, 1.0f);
    int e = (int)fl;
    return p * __int_as_float((e + 127) << 23);
}

__device__ __forceinline__ float tf32r(float x) {
    float y;
    asm("cvt.rna.tf32.f32 %0, %1;" : "=f"(y) : "f"(x));
    return y;
}

__device__ __forceinline__ void mma8(float& c0, float& c1, float& c2, float& c3,
                                     unsigned a0, unsigned a1, unsigned a2, unsigned a3,
                                     unsigned b0, unsigned b1) {
    asm volatile(
        "mma.sync.aligned.m16n8k8.row.col.f32.tf32.tf32.f32 "
        "{%0,%1,%2,%3}, {%4,%5,%6,%7}, {%8,%9}, {%0,%1,%2,%3};\n"
        : "+f"(c0), "+f"(c1), "+f"(c2), "+f"(c3)
        : "r"(a0), "r"(a1), "r"(a2), "r"(a3), "r"(b0), "r"(b1));
}

// ---------------------------------------------------------------------------
// 3xTF32 GEMM: C[4096,512] = A[4096,512] @ W[512,512] + bias
// Block 256 thr / 8 warps; tile 128x64; warp = 16 rows x 64 cols.
// ---------------------------------------------------------------------------
__global__ __launch_bounds__(256, 2) void gemm_mma(const float* __restrict__ A,
                                                   const float* __restrict__ W,
                                                   const float* __restrict__ bias,
                                                   float* __restrict__ C) {
    extern __shared__ float sg[];
    float (*As)[68] = (float(*)[68])sg;            // [128][68] raw fp32
    float (*Ws)[72] = (float(*)[72])(sg + 128*68); // [64][72]  raw fp32
    const int t = threadIdx.x, lane = t & 31, w = t >> 5;
    const int g = lane >> 2, c = lane & 3;
    const int n0 = blockIdx.x * 64, m0 = blockIdx.y * 128;

    float acc[8][4] = {};

    for (int k0 = 0; k0 < 512; k0 += 64) {
        __syncthreads();
        #pragma unroll
        for (int i = 0; i < 8; i++) {
            int idx = i*256 + t; int r = idx >> 4; int cg = (idx & 15) << 2;
            *(float4*)&As[r][cg] = *(const float4*)&A[(size_t)(m0 + r)*512 + k0 + cg];
        }
        #pragma unroll
        for (int i = 0; i < 4; i++) {
            int idx = i*256 + t; int r = idx >> 4; int cg = (idx & 15) << 2;
            *(float4*)&Ws[r][cg] = *(const float4*)&W[(size_t)(k0 + r)*512 + n0 + cg];
        }
        __syncthreads();

        unsigned ah[8][4], al[8][4];
        #pragma unroll
        for (int kk = 0; kk < 8; kk++) {
            float x0 = As[w*16 + g][kk*8 + c];
            float x1 = As[w*16 + g + 8][kk*8 + c];
            float x2 = As[w*16 + g][kk*8 + c + 4];
            float x3 = As[w*16 + g + 8][kk*8 + c + 4];
            float h0 = tf32r(x0), h1 = tf32r(x1), h2 = tf32r(x2), h3 = tf32r(x3);
            ah[kk][0] = __float_as_uint(h0); al[kk][0] = __float_as_uint(tf32r(x0 - h0));
            ah[kk][1] = __float_as_uint(h1); al[kk][1] = __float_as_uint(tf32r(x1 - h1));
            ah[kk][2] = __float_as_uint(h2); al[kk][2] = __float_as_uint(tf32r(x2 - h2));
            ah[kk][3] = __float_as_uint(h3); al[kk][3] = __float_as_uint(tf32r(x3 - h3));
        }
        #pragma unroll
        for (int nb = 0; nb < 8; nb++) {
            #pragma unroll
            for (int kk = 0; kk < 8; kk++) {
                float bx0 = Ws[kk*8 + c][nb*8 + g];
                float bx1 = Ws[kk*8 + c + 4][nb*8 + g];
                float bh0 = tf32r(bx0), bh1 = tf32r(bx1);
                unsigned uh0 = __float_as_uint(bh0), uh1 = __float_as_uint(bh1);
                unsigned ul0 = __float_as_uint(tf32r(bx0 - bh0));
                unsigned ul1 = __float_as_uint(tf32r(bx1 - bh1));
                mma8(acc[nb][0], acc[nb][1], acc[nb][2], acc[nb][3],
                     ah[kk][0], ah[kk][1], ah[kk][2], ah[kk][3], ul0, ul1);
                mma8(acc[nb][0], acc[nb][1], acc[nb][2], acc[nb][3],
                     al[kk][0], al[kk][1], al[kk][2], al[kk][3], uh0, uh1);
                mma8(acc[nb][0], acc[nb][1], acc[nb][2], acc[nb][3],
                     ah[kk][0], ah[kk][1], ah[kk][2], ah[kk][3], uh0, uh1);
            }
        }
    }
    #pragma unroll
    for (int nb = 0; nb < 8; nb++) {
        float2 bb = *(const float2*)&bias[n0 + nb*8 + 2*c];
        float2 o0 = {acc[nb][0] + bb.x, acc[nb][1] + bb.y};
        float2 o1 = {acc[nb][2] + bb.x, acc[nb][3] + bb.y};
        *(float2*)&C[(size_t)(m0 + w*16 + g)*512 + n0 + nb*8 + 2*c] = o0;
        *(float2*)&C[(size_t)(m0 + w*16 + g + 8)*512 + n0 + nb*8 + 2*c] = o1;
    }
}

// ---------------------------------------------------------------------------
// Flash attention, tf32 mma. Block: 128 q-rows, 8 warps (16 rows each), tiles of 64 keys.
// ---------------------------------------------------------------------------
__global__ __launch_bounds__(256, 2) void attn_mma(const float* __restrict__ Qp,
                                                   const float* __restrict__ Kp,
                                                   const float* __restrict__ Vp,
                                                   const float* __restrict__ bias,
                                                   const void* __restrict__ mask,
                                                   float* __restrict__ ctx) {
    extern __shared__ float sm[];
    float (*Qs)[68] = (float(*)[68])sm;                    // [128][68] tf32, prescaled
    float (*Ks)[68] = (float(*)[68])(sm + 128*68);         // [64][68]  Ks[kc][d]
    float (*Vs)[72] = (float(*)[72])(sm + 128*68 + 64*68); // [64][72]  Vs[kc][d]

    const int t = threadIdx.x, lane = t & 31, w = t >> 5;
    const int g = lane >> 2, c = lane & 3;
    const int q0 = blockIdx.x * 128;
    const int h = blockIdx.y, b = blockIdx.z;
    const int mode = g_mask_mode;

    const float* Qbase = Qp + (size_t)b*NS*HD + h*ND;
    const float* Kbase = Kp + (size_t)b*NS*HD + h*ND;
    const float* Vbase = Vp + (size_t)b*NS*HD + h*ND;
    const float* Bbase = bias + (size_t)h*NS*NS;

    #pragma unroll
    for (int i = 0; i < 8; i++) {
        int idx = i*256 + t; int r = idx >> 4; int cg = (idx & 15) << 2;
        float4 qv = *(const float4*)&Qbase[(size_t)(q0 + r)*HD + cg];
        qv.x = tf32r(qv.x * 0.125f); qv.y = tf32r(qv.y * 0.125f);
        qv.z = tf32r(qv.z * 0.125f); qv.w = tf32r(qv.w * 0.125f);
        *(float4*)&Qs[r][cg] = qv;
    }

    float mr[2] = {-1e30f, -1e30f}, lr[2] = {0.0f, 0.0f};
    float o[8][4] = {};
    const int rq0 = q0 + w*16 + g;
    const int sLo = (lane & 28) | (c >> 1);
    const int sHi = sLo + 2;
    const bool odd = c & 1;

    for (int k0 = 0; k0 < NS; k0 += 64) {
        __syncthreads();
        #pragma unroll
        for (int i = 0; i < 4; i++) {
            int idx = i*256 + t; int r = idx >> 4; int cg = (idx & 15) << 2;
            float4 kv = *(const float4*)&Kbase[(size_t)(k0 + r)*HD + cg];
            kv.x = tf32r(kv.x); kv.y = tf32r(kv.y); kv.z = tf32r(kv.z); kv.w = tf32r(kv.w);
            *(float4*)&Ks[r][cg] = kv;
            float4 vv = *(const float4*)&Vbase[(size_t)(k0 + r)*HD + cg];
            vv.x = tf32r(vv.x); vv.y = tf32r(vv.y); vv.z = tf32r(vv.z); vv.w = tf32r(vv.w);
            *(float4*)&Vs[r][cg] = vv;
        }
        __syncthreads();

        // S = Q K^T (16x64 per warp)
        unsigned a[8][4];
        #pragma unroll
        for (int kk = 0; kk < 8; kk++) {
            a[kk][0] = __float_as_uint(Qs[w*16 + g][kk*8 + c]);
            a[kk][1] = __float_as_uint(Qs[w*16 + g + 8][kk*8 + c]);
            a[kk][2] = __float_as_uint(Qs[w*16 + g][kk*8 + c + 4]);
            a[kk][3] = __float_as_uint(Qs[w*16 + g + 8][kk*8 + c + 4]);
        }
        float s[8][4];
        #pragma unroll
        for (int nb = 0; nb < 8; nb++) { s[nb][0]=0.f; s[nb][1]=0.f; s[nb][2]=0.f; s[nb][3]=0.f; }
        #pragma unroll
        for (int nb = 0; nb < 8; nb++) {
            #pragma unroll
            for (int kk = 0; kk < 8; kk++) {
                unsigned b0 = __float_as_uint(Ks[nb*8 + g][kk*8 + c]);
                unsigned b1 = __float_as_uint(Ks[nb*8 + g][kk*8 + c + 4]);
                mma8(s[nb][0], s[nb][1], s[nb][2], s[nb][3],
                     a[kk][0], a[kk][1], a[kk][2], a[kk][3], b0, b1);
            }
        }

        // bias + mask
        #pragma unroll
        for (int nb = 0; nb < 8; nb++) {
            #pragma unroll
            for (int hr = 0; hr < 2; hr++) {
                size_t off = (size_t)(rq0 + hr*8)*NS + (k0 + nb*8 + 2*c);
                float2 b2 = *(const float2*)&Bbase[off];
                unsigned ok0, ok1;
                if (mode == 1) {
                    int2 mm = *(const int2*)((const int*)mask + off);
                    ok0 = mm.x != 0; ok1 = mm.y != 0;
                } else if (mode == 2) {
                    float2 mm = *(const float2*)((const float*)mask + off);
                    ok0 = mm.x != 0.0f; ok1 = mm.y != 0.0f;
                } else {
                    unsigned short m2 = *(const unsigned short*)((const unsigned char*)mask + off);
                    ok0 = m2 & 0xFF; ok1 = m2 >> 8;
                }
                s[nb][hr*2+0] = ok0 ? s[nb][hr*2+0] + b2.x : -1e30f;
                s[nb][hr*2+1] = ok1 ? s[nb][hr*2+1] + b2.y : -1e30f;
            }
        }

        // online softmax (rows split across the 4 lanes of each group)
        #pragma unroll
        for (int hr = 0; hr < 2; hr++) {
            float tm = -1e30f;
            #pragma unroll
            for (int nb = 0; nb < 8; nb++)
                tm = fmaxf(tm, fmaxf(s[nb][hr*2], s[nb][hr*2+1]));
            tm = fmaxf(tm, __shfl_xor_sync(0xFFFFFFFFu, tm, 1));
            tm = fmaxf(tm, __shfl_xor_sync(0xFFFFFFFFu, tm, 2));
            float mn = fmaxf(mr[hr], tm);
            float scr = fexp(mr[hr] - mn);
            mr[hr] = mn;
            float ls = 0.0f;
            #pragma unroll
            for (int nb = 0; nb < 8; nb++) {
                float p0 = fexp(s[nb][hr*2] - mn);
                float p1 = fexp(s[nb][hr*2+1] - mn);
                s[nb][hr*2] = p0; s[nb][hr*2+1] = p1;
                ls += p0 + p1;
            }
            lr[hr] = lr[hr]*scr + ls;
            #pragma unroll
            for (int nb = 0; nb < 8; nb++) { o[nb][hr*2] *= scr; o[nb][hr*2+1] *= scr; }
        }

        // P (C-fragment) -> A-fragment via shuffles
        #pragma unroll
        for (int kk = 0; kk < 8; kk++) {
            float v0 = __shfl_sync(0xFFFFFFFFu, s[kk][0], sLo);
            float v1 = __shfl_sync(0xFFFFFFFFu, s[kk][1], sLo);
            float v2 = __shfl_sync(0xFFFFFFFFu, s[kk][2], sLo);
            float v3 = __shfl_sync(0xFFFFFFFFu, s[kk][3], sLo);
            float w0 = __shfl_sync(0xFFFFFFFFu, s[kk][0], sHi);
            float w1 = __shfl_sync(0xFFFFFFFFu, s[kk][1], sHi);
            float w2 = __shfl_sync(0xFFFFFFFFu, s[kk][2], sHi);
            float w3 = __shfl_sync(0xFFFFFFFFu, s[kk][3], sHi);
            a[kk][0] = __float_as_uint(tf32r(odd ? v1 : v0));
            a[kk][1] = __float_as_uint(tf32r(odd ? v3 : v2));
            a[kk][2] = __float_as_uint(tf32r(odd ? w1 : w0));
            a[kk][3] = __float_as_uint(tf32r(odd ? w3 : w2));
        }

        // O += P @ V
        #pragma unroll
        for (int nb = 0; nb < 8; nb++) {
            #pragma unroll
            for (int kk = 0; kk < 8; kk++) {
                unsigned b0 = __float_as_uint(Vs[kk*8 + c][nb*8 + g]);
                unsigned b1 = __float_as_uint(Vs[kk*8 + c + 4][nb*8 + g]);
                mma8(o[nb][0], o[nb][1], o[nb][2], o[nb][3],
                     a[kk][0], a[kk][1], a[kk][2], a[kk][3], b0, b1);
            }
        }
    }

    float lf0 = lr[0];
    lf0 += __shfl_xor_sync(0xFFFFFFFFu, lf0, 1);
    lf0 += __shfl_xor_sync(0xFFFFFFFFu, lf0, 2);
    float lf1 = lr[1];
    lf1 += __shfl_xor_sync(0xFFFFFFFFu, lf1, 1);
    lf1 += __shfl_xor_sync(0xFFFFFFFFu, lf1, 2);
    float inv0 = 1.0f / lf0, inv1 = 1.0f / lf1;

    #pragma unroll
    for (int nb = 0; nb < 8; nb++) {
        size_t row0 = (size_t)(b*NS + q0 + w*16 + g);
        float2 o0 = {o[nb][0]*inv0, o[nb][1]*inv0};
        float2 o1 = {o[nb][2]*inv1, o[nb][3]*inv1};
        *(float2*)&ctx[row0*HD + h*ND + nb*8 + 2*c] = o0;
        *(float2*)&ctx[(row0 + 8)*HD + h*ND + nb*8 + 2*c] = o1;
    }
}

extern "C" void kernel_launch(void* const* d_in, const int* in_sizes, int n_in,
                              void* d_out, int out_size) {
    const float* k    = (const float*)d_in[0];
    const float* v    = (const float*)d_in[1];
    const float* q    = (const float*)d_in[2];
    const void*  mask = d_in[3];
    const float* sbias = (const float*)d_in[4];
    const float* Wq = (const float*)d_in[5];
    const float* bq = (const float*)d_in[6];
    const float* Wk = (const float*)d_in[7];
    const float* bk = (const float*)d_in[8];
    const float* Wv = (const float*)d_in[9];
    const float* bv = (const float*)d_in[10];
    const float* Wo = (const float*)d_in[11];
    const float* bo = (const float*)d_in[12];
    float* out = (float*)d_out;

    float *qp, *kp, *vp, *ctx;
    cudaGetSymbolAddress((void**)&qp,  g_qp);
    cudaGetSymbolAddress((void**)&kp,  g_kp);
    cudaGetSymbolAddress((void**)&vp,  g_vp);
    cudaGetSymbolAddress((void**)&ctx, g_ctx);

    const int SMEM_G = (128*68 + 64*72) * 4;              // 53248
    const int SMEM_A = (128*68 + 64*68 + 64*72) * 4;      // 70656
    cudaFuncSetAttribute(gemm_mma, cudaFuncAttributeMaxDynamicSharedMemorySize, SMEM_G);
    cudaFuncSetAttribute(attn_mma, cudaFuncAttributeMaxDynamicSharedMemorySize, SMEM_A);

    detect_mask_kernel<<<1, 1>>>(mask);

    dim3 gb(8, 32);   // N/64, M/128
    gemm_mma<<<gb, 256, SMEM_G>>>(q, Wq, bq, qp);
    gemm_mma<<<gb, 256, SMEM_G>>>(k, Wk, bk, kp);
    gemm_mma<<<gb, 256, SMEM_G>>>(v, Wv, bv, vp);

    dim3 ga(NS / 128, NH, NB);
    attn_mma<<<ga, 256, SMEM_A>>>(qp, kp, vp, sbias, mask, ctx);

    gemm_mma<<<gb, 256, SMEM_G>>>(ctx, Wo, bo, out);
}

// round 5
// speedup vs baseline: 2.6866x; 1.2659x over previous
#include <cuda_runtime.h>
#include <cuda_bf16.h>
#include <math.h>
#include <stdint.h>

#define NB 2
#define NS 2048
#define NH 8
#define ND 64
#define HD 512

__device__ float g_qp[NB*NS*HD];
__device__ float g_kp[NB*NS*HD];
__device__ float g_vp[NB*NS*HD];
__device__ float g_ctx[NB*NS*HD];
__device__ int   g_mask_mode;

// packed bf16 hi/lo operands (k-pairs packed in one uint)
__device__ unsigned g_act_h[NB*NS*(HD/2)];   // activations [4096][256], reused
__device__ unsigned g_act_l[NB*NS*(HD/2)];
__device__ unsigned g_Wh[4][(HD/2)*HD];      // weights [256][512] x4 (q,k,v,o)
__device__ unsigned g_Wl[4][(HD/2)*HD];

__global__ void detect_mask_kernel(const void* mask) {
    const int*   mi = (const int*)mask;
    const float* mf = (const float*)mask;
    bool i32 = true, f32 = true;
    for (int i = 0; i < 16; i++) {
        int v = mi[i];
        if (v != 0 && v != 1) i32 = false;
        float f = mf[i];
        if (!(f == 0.0f || f == 1.0f)) f32 = false;
    }
    g_mask_mode = i32 ? 1 : (f32 ? 2 : 0);
}

__device__ __forceinline__ unsigned short bf16bits(float x) {
    __nv_bfloat16 b = __float2bfloat16(x);
    return *(unsigned short*)&b;
}
__device__ __forceinline__ float bf16val(unsigned short s) {
    __nv_bfloat16 b = *(__nv_bfloat16*)&s;
    return __bfloat162float(b);
}

// A[rows][512] fp32 -> Ah/Al [rows][256] uint (pairs of bf16 along k)
__global__ __launch_bounds__(256) void pack_act(const float* __restrict__ A,
                                                unsigned* __restrict__ Ah,
                                                unsigned* __restrict__ Al, int total) {
    int idx = blockIdx.x * 256 + threadIdx.x;
    if (idx >= total) return;
    float2 x = *(const float2*)&A[(size_t)idx * 2];
    unsigned short h0 = bf16bits(x.x), h1 = bf16bits(x.y);
    unsigned short l0 = bf16bits(x.x - bf16val(h0));
    unsigned short l1 = bf16bits(x.y - bf16val(h1));
    Ah[idx] = (unsigned)h0 | ((unsigned)h1 << 16);
    Al[idx] = (unsigned)l0 | ((unsigned)l1 << 16);
}

// W[512][512] fp32 -> Wh/Wl [256][512] uint: pack (k=2kp, k=2kp+1) per n
__global__ __launch_bounds__(256) void pack_w(const float* __restrict__ W,
                                              unsigned* __restrict__ Wh,
                                              unsigned* __restrict__ Wl) {
    int idx = blockIdx.x * 256 + threadIdx.x;   // 256*512 total
    int kp = idx >> 9, n = idx & 511;
    float w0 = W[(size_t)(2*kp) * 512 + n];
    float w1 = W[(size_t)(2*kp+1) * 512 + n];
    unsigned short h0 = bf16bits(w0), h1 = bf16bits(w1);
    unsigned short l0 = bf16bits(w0 - bf16val(h0));
    unsigned short l1 = bf16bits(w1 - bf16val(h1));
    Wh[idx] = (unsigned)h0 | ((unsigned)h1 << 16);
    Wl[idx] = (unsigned)l0 | ((unsigned)l1 << 16);
}

__device__ __forceinline__ float fexp(float x) {
    float z = x * 1.4426950408889634f;
    z = fmaxf(z, -120.0f);
    float fl = rintf(z);
    float f = z - fl;
    float p = 1.3333558e-3f;
    p = fmaf(p, f, 9.6181291e-3f);
    p = fmaf(p, f, 5.5504109e-2f);
    p = fmaf(p, f, 2.4022651e-1f);
    p = fmaf(p, f, 6.9314718e-1f);
    p = fmaf(p, f, 1.0f);
    int e = (int)fl;
    return p * __int_as_float((e + 127) << 23);
}

__device__ __forceinline__ float tf32r(float x) {
    float y;
    asm("cvt.rna.tf32.f32 %0, %1;" : "=f"(y) : "f"(x));
    return y;
}

__device__ __forceinline__ void mma8(float& c0, float& c1, float& c2, float& c3,
                                     unsigned a0, unsigned a1, unsigned a2, unsigned a3,
                                     unsigned b0, unsigned b1) {
    asm volatile(
        "mma.sync.aligned.m16n8k8.row.col.f32.tf32.tf32.f32 "
        "{%0,%1,%2,%3}, {%4,%5,%6,%7}, {%8,%9}, {%0,%1,%2,%3};\n"
        : "+f"(c0), "+f"(c1), "+f"(c2), "+f"(c3)
        : "r"(a0), "r"(a1), "r"(a2), "r"(a3), "r"(b0), "r"(b1));
}

__device__ __forceinline__ void mma16(float& c0, float& c1, float& c2, float& c3,
                                      unsigned a0, unsigned a1, unsigned a2, unsigned a3,
                                      unsigned b0, unsigned b1) {
    asm volatile(
        "mma.sync.aligned.m16n8k16.row.col.f32.bf16.bf16.f32 "
        "{%0,%1,%2,%3}, {%4,%5,%6,%7}, {%8,%9}, {%0,%1,%2,%3};\n"
        : "+f"(c0), "+f"(c1), "+f"(c2), "+f"(c3)
        : "r"(a0), "r"(a1), "r"(a2), "r"(a3), "r"(b0), "r"(b1));
}

// ---------------------------------------------------------------------------
// bf16 hi/lo split GEMM: C[4096,512] = A @ W + bias. Tile 128x64, 8 warps.
// A packed [4096][256] uint (k-pairs), W packed [256][512].
// ---------------------------------------------------------------------------
__global__ __launch_bounds__(256, 2) void gemm_bf16(const unsigned* __restrict__ Ah,
                                                    const unsigned* __restrict__ Al,
                                                    const unsigned* __restrict__ Wh,
                                                    const unsigned* __restrict__ Wl,
                                                    const float* __restrict__ bias,
                                                    float* __restrict__ C) {
    extern __shared__ unsigned su[];
    unsigned (*Ash)[36] = (unsigned(*)[36])su;              // [128][36]
    unsigned (*Asl)[36] = (unsigned(*)[36])(su + 128*36);
    unsigned (*Wsh)[72] = (unsigned(*)[72])(su + 2*128*36); // [32][72]
    unsigned (*Wsl)[72] = (unsigned(*)[72])(su + 2*128*36 + 32*72);

    const int t = threadIdx.x, lane = t & 31, w = t >> 5;
    const int g = lane >> 2, c = lane & 3;
    const int n0 = blockIdx.x * 64, m0 = blockIdx.y * 128;

    float acc[8][4] = {};

    for (int k0p = 0; k0p < 256; k0p += 32) {
        __syncthreads();
        #pragma unroll
        for (int i = 0; i < 4; i++) {
            int linear = i*256 + t;
            int r = linear >> 3, q = (linear & 7) << 2;
            *(uint4*)&Ash[r][q] = *(const uint4*)&Ah[(size_t)(m0 + r)*256 + k0p + q];
            *(uint4*)&Asl[r][q] = *(const uint4*)&Al[(size_t)(m0 + r)*256 + k0p + q];
        }
        #pragma unroll
        for (int i = 0; i < 2; i++) {
            int linear = i*256 + t;
            int r = linear >> 4, q = (linear & 15) << 2;
            *(uint4*)&Wsh[r][q] = *(const uint4*)&Wh[(size_t)(k0p + r)*512 + n0 + q];
            *(uint4*)&Wsl[r][q] = *(const uint4*)&Wl[(size_t)(k0p + r)*512 + n0 + q];
        }
        __syncthreads();

        #pragma unroll
        for (int kk = 0; kk < 4; kk++) {
            unsigned ah0 = Ash[w*16 + g][kk*8 + c];
            unsigned ah1 = Ash[w*16 + g + 8][kk*8 + c];
            unsigned ah2 = Ash[w*16 + g][kk*8 + c + 4];
            unsigned ah3 = Ash[w*16 + g + 8][kk*8 + c + 4];
            unsigned al0 = Asl[w*16 + g][kk*8 + c];
            unsigned al1 = Asl[w*16 + g + 8][kk*8 + c];
            unsigned al2 = Asl[w*16 + g][kk*8 + c + 4];
            unsigned al3 = Asl[w*16 + g + 8][kk*8 + c + 4];
            #pragma unroll
            for (int nb = 0; nb < 8; nb++) {
                unsigned bh0 = Wsh[kk*8 + c][nb*8 + g];
                unsigned bh1 = Wsh[kk*8 + c + 4][nb*8 + g];
                unsigned bl0 = Wsl[kk*8 + c][nb*8 + g];
                unsigned bl1 = Wsl[kk*8 + c + 4][nb*8 + g];
                mma16(acc[nb][0], acc[nb][1], acc[nb][2], acc[nb][3],
                      ah0, ah1, ah2, ah3, bh0, bh1);
                mma16(acc[nb][0], acc[nb][1], acc[nb][2], acc[nb][3],
                      ah0, ah1, ah2, ah3, bl0, bl1);
                mma16(acc[nb][0], acc[nb][1], acc[nb][2], acc[nb][3],
                      al0, al1, al2, al3, bh0, bh1);
            }
        }
    }
    #pragma unroll
    for (int nb = 0; nb < 8; nb++) {
        float2 bb = *(const float2*)&bias[n0 + nb*8 + 2*c];
        float2 o0 = {acc[nb][0] + bb.x, acc[nb][1] + bb.y};
        float2 o1 = {acc[nb][2] + bb.x, acc[nb][3] + bb.y};
        *(float2*)&C[(size_t)(m0 + w*16 + g)*512 + n0 + nb*8 + 2*c] = o0;
        *(float2*)&C[(size_t)(m0 + w*16 + g + 8)*512 + n0 + nb*8 + 2*c] = o1;
    }
}

// ---------------------------------------------------------------------------
// Flash attention, tf32 mma (unchanged from passing R4 kernel)
// ---------------------------------------------------------------------------
__global__ __launch_bounds__(256, 2) void attn_mma(const float* __restrict__ Qp,
                                                   const float* __restrict__ Kp,
                                                   const float* __restrict__ Vp,
                                                   const float* __restrict__ bias,
                                                   const void* __restrict__ mask,
                                                   float* __restrict__ ctx) {
    extern __shared__ float sm[];
    float (*Qs)[68] = (float(*)[68])sm;
    float (*Ks)[68] = (float(*)[68])(sm + 128*68);
    float (*Vs)[72] = (float(*)[72])(sm + 128*68 + 64*68);

    const int t = threadIdx.x, lane = t & 31, w = t >> 5;
    const int g = lane >> 2, c = lane & 3;
    const int q0 = blockIdx.x * 128;
    const int h = blockIdx.y, b = blockIdx.z;
    const int mode = g_mask_mode;

    const float* Qbase = Qp + (size_t)b*NS*HD + h*ND;
    const float* Kbase = Kp + (size_t)b*NS*HD + h*ND;
    const float* Vbase = Vp + (size_t)b*NS*HD + h*ND;
    const float* Bbase = bias + (size_t)h*NS*NS;

    #pragma unroll
    for (int i = 0; i < 8; i++) {
        int idx = i*256 + t; int r = idx >> 4; int cg = (idx & 15) << 2;
        float4 qv = *(const float4*)&Qbase[(size_t)(q0 + r)*HD + cg];
        qv.x = tf32r(qv.x * 0.125f); qv.y = tf32r(qv.y * 0.125f);
        qv.z = tf32r(qv.z * 0.125f); qv.w = tf32r(qv.w * 0.125f);
        *(float4*)&Qs[r][cg] = qv;
    }

    float mr[2] = {-1e30f, -1e30f}, lr[2] = {0.0f, 0.0f};
    float o[8][4] = {};
    const int rq0 = q0 + w*16 + g;
    const int sLo = (lane & 28) | (c >> 1);
    const int sHi = sLo + 2;
    const bool odd = c & 1;

    for (int k0 = 0; k0 < NS; k0 += 64) {
        __syncthreads();
        #pragma unroll
        for (int i = 0; i < 4; i++) {
            int idx = i*256 + t; int r = idx >> 4; int cg = (idx & 15) << 2;
            float4 kv = *(const float4*)&Kbase[(size_t)(k0 + r)*HD + cg];
            kv.x = tf32r(kv.x); kv.y = tf32r(kv.y); kv.z = tf32r(kv.z); kv.w = tf32r(kv.w);
            *(float4*)&Ks[r][cg] = kv;
            float4 vv = *(const float4*)&Vbase[(size_t)(k0 + r)*HD + cg];
            vv.x = tf32r(vv.x); vv.y = tf32r(vv.y); vv.z = tf32r(vv.z); vv.w = tf32r(vv.w);
            *(float4*)&Vs[r][cg] = vv;
        }
        __syncthreads();

        unsigned a[8][4];
        #pragma unroll
        for (int kk = 0; kk < 8; kk++) {
            a[kk][0] = __float_as_uint(Qs[w*16 + g][kk*8 + c]);
            a[kk][1] = __float_as_uint(Qs[w*16 + g + 8][kk*8 + c]);
            a[kk][2] = __float_as_uint(Qs[w*16 + g][kk*8 + c + 4]);
            a[kk][3] = __float_as_uint(Qs[w*16 + g + 8][kk*8 + c + 4]);
        }
        float s[8][4];
        #pragma unroll
        for (int nb = 0; nb < 8; nb++) { s[nb][0]=0.f; s[nb][1]=0.f; s[nb][2]=0.f; s[nb][3]=0.f; }
        #pragma unroll
        for (int nb = 0; nb < 8; nb++) {
            #pragma unroll
            for (int kk = 0; kk < 8; kk++) {
                unsigned b0 = __float_as_uint(Ks[nb*8 + g][kk*8 + c]);
                unsigned b1 = __float_as_uint(Ks[nb*8 + g][kk*8 + c + 4]);
                mma8(s[nb][0], s[nb][1], s[nb][2], s[nb][3],
                     a[kk][0], a[kk][1], a[kk][2], a[kk][3], b0, b1);
            }
        }

        #pragma unroll
        for (int nb = 0; nb < 8; nb++) {
            #pragma unroll
            for (int hr = 0; hr < 2; hr++) {
                size_t off = (size_t)(rq0 + hr*8)*NS + (k0 + nb*8 + 2*c);
                float2 b2 = *(const float2*)&Bbase[off];
                unsigned ok0, ok1;
                if (mode == 1) {
                    int2 mm = *(const int2*)((const int*)mask + off);
                    ok0 = mm.x != 0; ok1 = mm.y != 0;
                } else if (mode == 2) {
                    float2 mm = *(const float2*)((const float*)mask + off);
                    ok0 = mm.x != 0.0f; ok1 = mm.y != 0.0f;
                } else {
                    unsigned short m2 = *(const unsigned short*)((const unsigned char*)mask + off);
                    ok0 = m2 & 0xFF; ok1 = m2 >> 8;
                }
                s[nb][hr*2+0] = ok0 ? s[nb][hr*2+0] + b2.x : -1e30f;
                s[nb][hr*2+1] = ok1 ? s[nb][hr*2+1] + b2.y : -1e30f;
            }
        }

        #pragma unroll
        for (int hr = 0; hr < 2; hr++) {
            float tm = -1e30f;
            #pragma unroll
            for (int nb = 0; nb < 8; nb++)
                tm = fmaxf(tm, fmaxf(s[nb][hr*2], s[nb][hr*2+1]));
            tm = fmaxf(tm, __shfl_xor_sync(0xFFFFFFFFu, tm, 1));
            tm = fmaxf(tm, __shfl_xor_sync(0xFFFFFFFFu, tm, 2));
            float mn = fmaxf(mr[hr], tm);
            float scr = fexp(mr[hr] - mn);
            mr[hr] = mn;
            float ls = 0.0f;
            #pragma unroll
            for (int nb = 0; nb < 8; nb++) {
                float p0 = fexp(s[nb][hr*2] - mn);
                float p1 = fexp(s[nb][hr*2+1] - mn);
                s[nb][hr*2] = p0; s[nb][hr*2+1] = p1;
                ls += p0 + p1;
            }
            lr[hr] = lr[hr]*scr + ls;
            #pragma unroll
            for (int nb = 0; nb < 8; nb++) { o[nb][hr*2] *= scr; o[nb][hr*2+1] *= scr; }
        }

        #pragma unroll
        for (int kk = 0; kk < 8; kk++) {
            float v0 = __shfl_sync(0xFFFFFFFFu, s[kk][0], sLo);
            float v1 = __shfl_sync(0xFFFFFFFFu, s[kk][1], sLo);
            float v2 = __shfl_sync(0xFFFFFFFFu, s[kk][2], sLo);
            float v3 = __shfl_sync(0xFFFFFFFFu, s[kk][3], sLo);
            float w0 = __shfl_sync(0xFFFFFFFFu, s[kk][0], sHi);
            float w1 = __shfl_sync(0xFFFFFFFFu, s[kk][1], sHi);
            float w2 = __shfl_sync(0xFFFFFFFFu, s[kk][2], sHi);
            float w3 = __shfl_sync(0xFFFFFFFFu, s[kk][3], sHi);
            a[kk][0] = __float_as_uint(tf32r(odd ? v1 : v0));
            a[kk][1] = __float_as_uint(tf32r(odd ? v3 : v2));
            a[kk][2] = __float_as_uint(tf32r(odd ? w1 : w0));
            a[kk][3] = __float_as_uint(tf32r(odd ? w3 : w2));
        }

        #pragma unroll
        for (int nb = 0; nb < 8; nb++) {
            #pragma unroll
            for (int kk = 0; kk < 8; kk++) {
                unsigned b0 = __float_as_uint(Vs[kk*8 + c][nb*8 + g]);
                unsigned b1 = __float_as_uint(Vs[kk*8 + c + 4][nb*8 + g]);
                mma8(o[nb][0], o[nb][1], o[nb][2], o[nb][3],
                     a[kk][0], a[kk][1], a[kk][2], a[kk][3], b0, b1);
            }
        }
    }

    float lf0 = lr[0];
    lf0 += __shfl_xor_sync(0xFFFFFFFFu, lf0, 1);
    lf0 += __shfl_xor_sync(0xFFFFFFFFu, lf0, 2);
    float lf1 = lr[1];
    lf1 += __shfl_xor_sync(0xFFFFFFFFu, lf1, 1);
    lf1 += __shfl_xor_sync(0xFFFFFFFFu, lf1, 2);
    float inv0 = 1.0f / lf0, inv1 = 1.0f / lf1;

    #pragma unroll
    for (int nb = 0; nb < 8; nb++) {
        size_t row0 = (size_t)(b*NS + q0 + w*16 + g);
        float2 o0 = {o[nb][0]*inv0, o[nb][1]*inv0};
        float2 o1 = {o[nb][2]*inv1, o[nb][3]*inv1};
        *(float2*)&ctx[row0*HD + h*ND + nb*8 + 2*c] = o0;
        *(float2*)&ctx[(row0 + 8)*HD + h*ND + nb*8 + 2*c] = o1;
    }
}

extern "C" void kernel_launch(void* const* d_in, const int* in_sizes, int n_in,
                              void* d_out, int out_size) {
    const float* k    = (const float*)d_in[0];
    const float* v    = (const float*)d_in[1];
    const float* q    = (const float*)d_in[2];
    const void*  mask = d_in[3];
    const float* sbias = (const float*)d_in[4];
    const float* Wq = (const float*)d_in[5];
    const float* bq = (const float*)d_in[6];
    const float* Wk = (const float*)d_in[7];
    const float* bk = (const float*)d_in[8];
    const float* Wv = (const float*)d_in[9];
    const float* bv = (const float*)d_in[10];
    const float* Wo = (const float*)d_in[11];
    const float* bo = (const float*)d_in[12];
    float* out = (float*)d_out;

    float *qp, *kp, *vp, *ctx;
    unsigned *ah, *al, *wh, *wl;
    cudaGetSymbolAddress((void**)&qp,  g_qp);
    cudaGetSymbolAddress((void**)&kp,  g_kp);
    cudaGetSymbolAddress((void**)&vp,  g_vp);
    cudaGetSymbolAddress((void**)&ctx, g_ctx);
    cudaGetSymbolAddress((void**)&ah,  g_act_h);
    cudaGetSymbolAddress((void**)&al,  g_act_l);
    cudaGetSymbolAddress((void**)&wh,  g_Wh);
    cudaGetSymbolAddress((void**)&wl,  g_Wl);

    const int WSZ = (HD/2)*HD;  // 131072 uints per weight matrix
    const int SMEM_G = (2*128*36 + 2*32*72) * 4;          // 55296
    const int SMEM_A = (128*68 + 64*68 + 64*72) * 4;      // 70656
    cudaFuncSetAttribute(gemm_bf16, cudaFuncAttributeMaxDynamicSharedMemorySize, SMEM_G);
    cudaFuncSetAttribute(attn_mma,  cudaFuncAttributeMaxDynamicSharedMemorySize, SMEM_A);

    detect_mask_kernel<<<1, 1>>>(mask);

    // pack the 4 weight matrices
    pack_w<<<512, 256>>>(Wq, wh + 0*WSZ, wl + 0*WSZ);
    pack_w<<<512, 256>>>(Wk, wh + 1*WSZ, wl + 1*WSZ);
    pack_w<<<512, 256>>>(Wv, wh + 2*WSZ, wl + 2*WSZ);
    pack_w<<<512, 256>>>(Wo, wh + 3*WSZ, wl + 3*WSZ);

    const int ACT_TOT = NB*NS*(HD/2);   // 1,048,576
    dim3 gb(8, 32);

    pack_act<<<ACT_TOT/256, 256>>>(q, ah, al, ACT_TOT);
    gemm_bf16<<<gb, 256, SMEM_G>>>(ah, al, wh + 0*WSZ, wl + 0*WSZ, bq, qp);
    pack_act<<<ACT_TOT/256, 256>>>(k, ah, al, ACT_TOT);
    gemm_bf16<<<gb, 256, SMEM_G>>>(ah, al, wh + 1*WSZ, wl + 1*WSZ, bk, kp);
    pack_act<<<ACT_TOT/256, 256>>>(v, ah, al, ACT_TOT);
    gemm_bf16<<<gb, 256, SMEM_G>>>(ah, al, wh + 2*WSZ, wl + 2*WSZ, bv, vp);

    dim3 ga(NS / 128, NH, NB);
    attn_mma<<<ga, 256, SMEM_A>>>(qp, kp, vp, sbias, mask, ctx);

    pack_act<<<ACT_TOT/256, 256>>>(ctx, ah, al, ACT_TOT);
    gemm_bf16<<<gb, 256, SMEM_G>>>(ah, al, wh + 3*WSZ, wl + 3*WSZ, bo, out);
}

// round 7
// speedup vs baseline: 3.3702x; 1.2545x over previous
#include <cuda_runtime.h>
#include <cuda_bf16.h>
#include <math.h>
#include <stdint.h>

#define NB 2
#define NS 2048
#define NH 8
#define ND 64
#define HD 512
#define L2E 1.4426950408889634f

__device__ float g_qp[NB*NS*HD];
__device__ float g_kp[NB*NS*HD];
__device__ float g_vp[NB*NS*HD];
__device__ float g_ctx[NB*NS*HD];
__device__ int   g_mask_mode;
__device__ unsigned g_mbits[NS*(NS/32)];     // bit-packed mask [2048][64]

// packed bf16 hi/lo operands for projection GEMMs
__device__ unsigned g_act_h[NB*NS*(HD/2)];
__device__ unsigned g_act_l[NB*NS*(HD/2)];
__device__ unsigned g_Wh[4][(HD/2)*HD];
__device__ unsigned g_Wl[4][(HD/2)*HD];

__global__ void detect_mask_kernel(const void* mask) {
    const int*   mi = (const int*)mask;
    const float* mf = (const float*)mask;
    bool i32 = true, f32 = true;
    for (int i = 0; i < 16; i++) {
        int v = mi[i];
        if (v != 0 && v != 1) i32 = false;
        float f = mf[i];
        if (!(f == 0.0f || f == 1.0f)) f32 = false;
    }
    g_mask_mode = i32 ? 1 : (f32 ? 2 : 0);
}

// bit-pack mask: one thread per element, ballot per warp
__global__ __launch_bounds__(256) void bitpack_mask(const void* mask) {
    int id = blockIdx.x * 256 + threadIdx.x;      // 0 .. 2048*2048-1
    int mode = g_mask_mode;
    bool on;
    if (mode == 1)      on = ((const int*)mask)[id] != 0;
    else if (mode == 2) on = ((const float*)mask)[id] != 0.0f;
    else                on = ((const unsigned char*)mask)[id] != 0;
    unsigned bw = __ballot_sync(0xFFFFFFFFu, on);
    if ((threadIdx.x & 31) == 0) g_mbits[id >> 5] = bw;
}

__device__ __forceinline__ unsigned short bf16bits(float x) {
    __nv_bfloat16 b = __float2bfloat16(x);
    return *(unsigned short*)&b;
}
__device__ __forceinline__ float bf16val(unsigned short s) {
    __nv_bfloat16 b = *(__nv_bfloat16*)&s;
    return __bfloat162float(b);
}

__global__ __launch_bounds__(256) void pack_act(const float* __restrict__ A,
                                                unsigned* __restrict__ Ah,
                                                unsigned* __restrict__ Al, int total) {
    int idx = blockIdx.x * 256 + threadIdx.x;
    if (idx >= total) return;
    float2 x = *(const float2*)&A[(size_t)idx * 2];
    unsigned short h0 = bf16bits(x.x), h1 = bf16bits(x.y);
    unsigned short l0 = bf16bits(x.x - bf16val(h0));
    unsigned short l1 = bf16bits(x.y - bf16val(h1));
    Ah[idx] = (unsigned)h0 | ((unsigned)h1 << 16);
    Al[idx] = (unsigned)l0 | ((unsigned)l1 << 16);
}

__global__ __launch_bounds__(256) void pack_w(const float* __restrict__ W,
                                              unsigned* __restrict__ Wh,
                                              unsigned* __restrict__ Wl) {
    int idx = blockIdx.x * 256 + threadIdx.x;
    int kp = idx >> 9, n = idx & 511;
    float w0 = W[(size_t)(2*kp) * 512 + n];
    float w1 = W[(size_t)(2*kp+1) * 512 + n];
    unsigned short h0 = bf16bits(w0), h1 = bf16bits(w1);
    unsigned short l0 = bf16bits(w0 - bf16val(h0));
    unsigned short l1 = bf16bits(w1 - bf16val(h1));
    Wh[idx] = (unsigned)h0 | ((unsigned)h1 << 16);
    Wl[idx] = (unsigned)l0 | ((unsigned)l1 << 16);
}

__device__ __forceinline__ float ex2f(float x) {
    float y;
    asm("ex2.approx.ftz.f32 %0, %1;" : "=f"(y) : "f"(x));
    return y;
}

__device__ __forceinline__ unsigned packh2(float lo, float hi) {
    unsigned r;
    asm("cvt.rn.f16x2.f32 %0, %1, %2;" : "=r"(r) : "f"(hi), "f"(lo));
    return r;
}

__device__ __forceinline__ void mma16(float& c0, float& c1, float& c2, float& c3,
                                      unsigned a0, unsigned a1, unsigned a2, unsigned a3,
                                      unsigned b0, unsigned b1) {
    asm volatile(
        "mma.sync.aligned.m16n8k16.row.col.f32.bf16.bf16.f32 "
        "{%0,%1,%2,%3}, {%4,%5,%6,%7}, {%8,%9}, {%0,%1,%2,%3};\n"
        : "+f"(c0), "+f"(c1), "+f"(c2), "+f"(c3)
        : "r"(a0), "r"(a1), "r"(a2), "r"(a3), "r"(b0), "r"(b1));
}

__device__ __forceinline__ void mma16h(float& c0, float& c1, float& c2, float& c3,
                                       unsigned a0, unsigned a1, unsigned a2, unsigned a3,
                                       unsigned b0, unsigned b1) {
    asm volatile(
        "mma.sync.aligned.m16n8k16.row.col.f32.f16.f16.f32 "
        "{%0,%1,%2,%3}, {%4,%5,%6,%7}, {%8,%9}, {%0,%1,%2,%3};\n"
        : "+f"(c0), "+f"(c1), "+f"(c2), "+f"(c3)
        : "r"(a0), "r"(a1), "r"(a2), "r"(a3), "r"(b0), "r"(b1));
}

// ---------------------------------------------------------------------------
// bf16 hi/lo split GEMM: C[4096,512] = A @ W + bias. Tile 128x64, 8 warps.
// ---------------------------------------------------------------------------
__global__ __launch_bounds__(256, 2) void gemm_bf16(const unsigned* __restrict__ Ah,
                                                    const unsigned* __restrict__ Al,
                                                    const unsigned* __restrict__ Wh,
                                                    const unsigned* __restrict__ Wl,
                                                    const float* __restrict__ bias,
                                                    float* __restrict__ C) {
    extern __shared__ unsigned su[];
    unsigned (*Ash)[36] = (unsigned(*)[36])su;
    unsigned (*Asl)[36] = (unsigned(*)[36])(su + 128*36);
    unsigned (*Wsh)[72] = (unsigned(*)[72])(su + 2*128*36);
    unsigned (*Wsl)[72] = (unsigned(*)[72])(su + 2*128*36 + 32*72);

    const int t = threadIdx.x, lane = t & 31, w = t >> 5;
    const int g = lane >> 2, c = lane & 3;
    const int n0 = blockIdx.x * 64, m0 = blockIdx.y * 128;

    float acc[8][4] = {};

    for (int k0p = 0; k0p < 256; k0p += 32) {
        __syncthreads();
        #pragma unroll
        for (int i = 0; i < 4; i++) {
            int linear = i*256 + t;
            int r = linear >> 3, q = (linear & 7) << 2;
            *(uint4*)&Ash[r][q] = *(const uint4*)&Ah[(size_t)(m0 + r)*256 + k0p + q];
            *(uint4*)&Asl[r][q] = *(const uint4*)&Al[(size_t)(m0 + r)*256 + k0p + q];
        }
        #pragma unroll
        for (int i = 0; i < 2; i++) {
            int linear = i*256 + t;
            int r = linear >> 4, q = (linear & 15) << 2;
            *(uint4*)&Wsh[r][q] = *(const uint4*)&Wh[(size_t)(k0p + r)*512 + n0 + q];
            *(uint4*)&Wsl[r][q] = *(const uint4*)&Wl[(size_t)(k0p + r)*512 + n0 + q];
        }
        __syncthreads();

        #pragma unroll
        for (int kk = 0; kk < 4; kk++) {
            unsigned ah0 = Ash[w*16 + g][kk*8 + c];
            unsigned ah1 = Ash[w*16 + g + 8][kk*8 + c];
            unsigned ah2 = Ash[w*16 + g][kk*8 + c + 4];
            unsigned ah3 = Ash[w*16 + g + 8][kk*8 + c + 4];
            unsigned al0 = Asl[w*16 + g][kk*8 + c];
            unsigned al1 = Asl[w*16 + g + 8][kk*8 + c];
            unsigned al2 = Asl[w*16 + g][kk*8 + c + 4];
            unsigned al3 = Asl[w*16 + g + 8][kk*8 + c + 4];
            #pragma unroll
            for (int nb = 0; nb < 8; nb++) {
                unsigned bh0 = Wsh[kk*8 + c][nb*8 + g];
                unsigned bh1 = Wsh[kk*8 + c + 4][nb*8 + g];
                unsigned bl0 = Wsl[kk*8 + c][nb*8 + g];
                unsigned bl1 = Wsl[kk*8 + c + 4][nb*8 + g];
                mma16(acc[nb][0], acc[nb][1], acc[nb][2], acc[nb][3],
                      ah0, ah1, ah2, ah3, bh0, bh1);
                mma16(acc[nb][0], acc[nb][1], acc[nb][2], acc[nb][3],
                      ah0, ah1, ah2, ah3, bl0, bl1);
                mma16(acc[nb][0], acc[nb][1], acc[nb][2], acc[nb][3],
                      al0, al1, al2, al3, bh0, bh1);
            }
        }
    }
    #pragma unroll
    for (int nb = 0; nb < 8; nb++) {
        float2 bb = *(const float2*)&bias[n0 + nb*8 + 2*c];
        float2 o0 = {acc[nb][0] + bb.x, acc[nb][1] + bb.y};
        float2 o1 = {acc[nb][2] + bb.x, acc[nb][3] + bb.y};
        *(float2*)&C[(size_t)(m0 + w*16 + g)*512 + n0 + nb*8 + 2*c] = o0;
        *(float2*)&C[(size_t)(m0 + w*16 + g + 8)*512 + n0 + nb*8 + 2*c] = o1;
    }
}

// ---------------------------------------------------------------------------
// fp16 flash attention. Block = 128 q-rows x 1 head x BOTH batches. 8 warps.
// grid (16, 8). Bias loaded once per tile (2nd batch hits L1/L2). Mask from bits.
// ---------------------------------------------------------------------------
__global__ __launch_bounds__(256, 1) void attn_fp16(const float* __restrict__ Qp,
                                                    const float* __restrict__ Kp,
                                                    const float* __restrict__ Vp,
                                                    const float* __restrict__ bias,
                                                    float* __restrict__ ctx) {
    __shared__ unsigned Ks[2][64][36];   // [batch][key][kpair]  fp16x2 along d
    __shared__ unsigned Vs[2][32][72];   // [batch][keypair][d]  fp16x2 along keys

    const int t = threadIdx.x, lane = t & 31, w = t >> 5;
    const int g = lane >> 2, c = lane & 3;
    const int q0 = blockIdx.x * 128;
    const int h = blockIdx.y;
    const int rq0 = q0 + w*16 + g;
    const size_t hOff = (size_t)h * ND;

    // Q fragments in registers (both batches), pre-scaled by 0.125
    unsigned qa[2][4][4];
    #pragma unroll
    for (int b = 0; b < 2; b++) {
        const float* Qb = Qp + ((size_t)(b*NS + rq0))*HD + hOff;
        #pragma unroll
        for (int kk = 0; kk < 4; kk++) {
            float2 x0 = *(const float2*)&Qb[16*kk + 2*c];
            float2 x1 = *(const float2*)&Qb[8*HD + 16*kk + 2*c];
            float2 x2 = *(const float2*)&Qb[16*kk + 2*c + 8];
            float2 x3 = *(const float2*)&Qb[8*HD + 16*kk + 2*c + 8];
            qa[b][kk][0] = packh2(x0.x*0.125f, x0.y*0.125f);
            qa[b][kk][1] = packh2(x1.x*0.125f, x1.y*0.125f);
            qa[b][kk][2] = packh2(x2.x*0.125f, x2.y*0.125f);
            qa[b][kk][3] = packh2(x3.x*0.125f, x3.y*0.125f);
        }
    }

    float mr[2][2], lr[2][2], o[2][8][4];
    #pragma unroll
    for (int b = 0; b < 2; b++) {
        mr[b][0] = mr[b][1] = -1e30f;
        lr[b][0] = lr[b][1] = 0.0f;
        #pragma unroll
        for (int nb = 0; nb < 8; nb++)
            #pragma unroll
            for (int j = 0; j < 4; j++) o[b][nb][j] = 0.0f;
    }

    for (int k0 = 0; k0 < NS; k0 += 64) {
        __syncthreads();
        // K tiles: fp16 pairs along d
        #pragma unroll
        for (int b = 0; b < 2; b++)
            #pragma unroll
            for (int i = 0; i < 4; i++) {
                int idx = i*256 + t;
                int r = idx >> 4, p2 = (idx & 15) * 2;
                float4 kv = *(const float4*)&Kp[((size_t)(b*NS + k0 + r))*HD + hOff + p2*2];
                Ks[b][r][p2]   = packh2(kv.x, kv.y);
                Ks[b][r][p2+1] = packh2(kv.z, kv.w);
            }
        // V tiles: fp16 pairs along keys (transposed pair packing)
        #pragma unroll
        for (int b = 0; b < 2; b++)
            #pragma unroll
            for (int i = 0; i < 8; i++) {
                int idx = i*256 + t;
                int kpi = idx >> 6, d = idx & 63;
                const float* Vb = Vp + ((size_t)(b*NS + k0 + 2*kpi))*HD + hOff + d;
                Vs[b][kpi][d] = packh2(Vb[0], Vb[HD]);
            }
        __syncthreads();

        #pragma unroll
        for (int b = 0; b < 2; b++) {
            // S = Q K^T
            float s[8][4];
            #pragma unroll
            for (int nb = 0; nb < 8; nb++) { s[nb][0]=0.f; s[nb][1]=0.f; s[nb][2]=0.f; s[nb][3]=0.f; }
            #pragma unroll
            for (int nb = 0; nb < 8; nb++)
                #pragma unroll
                for (int kk = 0; kk < 4; kk++)
                    mma16h(s[nb][0], s[nb][1], s[nb][2], s[nb][3],
                           qa[b][kk][0], qa[b][kk][1], qa[b][kk][2], qa[b][kk][3],
                           Ks[b][nb*8 + g][kk*8 + c], Ks[b][nb*8 + g][kk*8 + c + 4]);

            // mask words for this tile (2 rows x 64 keys = 2x2 uints)
            unsigned mw[2][2];
            #pragma unroll
            for (int hr = 0; hr < 2; hr++) {
                uint2 ww = *(const uint2*)&g_mbits[(size_t)(rq0 + hr*8)*(NS/32) + (k0 >> 5)];
                mw[hr][0] = ww.x; mw[hr][1] = ww.y;
            }

            // bias + mask
            #pragma unroll
            for (int nb = 0; nb < 8; nb++) {
                int j = nb*8 + 2*c;
                #pragma unroll
                for (int hr = 0; hr < 2; hr++) {
                    float2 b2 = *(const float2*)&bias[((size_t)h*NS + rq0 + hr*8)*NS + k0 + j];
                    unsigned word = mw[hr][j >> 5];
                    s[nb][hr*2]   = ((word >> (j & 31)) & 1)       ? s[nb][hr*2]   + b2.x : -1e30f;
                    s[nb][hr*2+1] = ((word >> ((j+1) & 31)) & 1)   ? s[nb][hr*2+1] + b2.y : -1e30f;
                }
            }

            // online softmax
            #pragma unroll
            for (int hr = 0; hr < 2; hr++) {
                float tm = fmaxf(s[0][hr*2], s[0][hr*2+1]);
                #pragma unroll
                for (int nb = 1; nb < 8; nb++)
                    tm = fmaxf(tm, fmaxf(s[nb][hr*2], s[nb][hr*2+1]));
                tm = fmaxf(tm, __shfl_xor_sync(0xFFFFFFFFu, tm, 1));
                tm = fmaxf(tm, __shfl_xor_sync(0xFFFFFFFFu, tm, 2));
                float mn = fmaxf(mr[b][hr], tm);
                float sc = ex2f((mr[b][hr] - mn) * L2E);
                float mnl = mn * L2E;
                mr[b][hr] = mn;
                float ls = 0.0f;
                #pragma unroll
                for (int nb = 0; nb < 8; nb++) {
                    float p0 = ex2f(fmaf(s[nb][hr*2],   L2E, -mnl));
                    float p1 = ex2f(fmaf(s[nb][hr*2+1], L2E, -mnl));
                    s[nb][hr*2] = p0; s[nb][hr*2+1] = p1;
                    ls += p0 + p1;
                }
                lr[b][hr] = lr[b][hr]*sc + ls;
                #pragma unroll
                for (int nb = 0; nb < 8; nb++) { o[b][nb][hr*2] *= sc; o[b][nb][hr*2+1] *= sc; }
            }

            // P (C-frag) -> A-frag: pure in-lane fp16 packing, no shuffles
            unsigned pa[4][4];
            #pragma unroll
            for (int kk = 0; kk < 4; kk++) {
                pa[kk][0] = packh2(s[2*kk][0],   s[2*kk][1]);
                pa[kk][1] = packh2(s[2*kk][2],   s[2*kk][3]);
                pa[kk][2] = packh2(s[2*kk+1][0], s[2*kk+1][1]);
                pa[kk][3] = packh2(s[2*kk+1][2], s[2*kk+1][3]);
            }

            // O += P V
            #pragma unroll
            for (int nb = 0; nb < 8; nb++)
                #pragma unroll
                for (int kk = 0; kk < 4; kk++)
                    mma16h(o[b][nb][0], o[b][nb][1], o[b][nb][2], o[b][nb][3],
                           pa[kk][0], pa[kk][1], pa[kk][2], pa[kk][3],
                           Vs[b][kk*8 + c][nb*8 + g], Vs[b][kk*8 + c + 4][nb*8 + g]);
        }
    }

    // epilogue
    #pragma unroll
    for (int b = 0; b < 2; b++) {
        float lf0 = lr[b][0];
        lf0 += __shfl_xor_sync(0xFFFFFFFFu, lf0, 1);
        lf0 += __shfl_xor_sync(0xFFFFFFFFu, lf0, 2);
        float lf1 = lr[b][1];
        lf1 += __shfl_xor_sync(0xFFFFFFFFu, lf1, 1);
        lf1 += __shfl_xor_sync(0xFFFFFFFFu, lf1, 2);
        float inv0 = 1.0f / lf0, inv1 = 1.0f / lf1;
        #pragma unroll
        for (int nb = 0; nb < 8; nb++) {
            size_t row0 = (size_t)(b*NS + rq0);
            float2 o0 = {o[b][nb][0]*inv0, o[b][nb][1]*inv0};
            float2 o1 = {o[b][nb][2]*inv1, o[b][nb][3]*inv1};
            *(float2*)&ctx[row0*HD + hOff + nb*8 + 2*c] = o0;
            *(float2*)&ctx[(row0 + 8)*HD + hOff + nb*8 + 2*c] = o1;
        }
    }
}

extern "C" void kernel_launch(void* const* d_in, const int* in_sizes, int n_in,
                              void* d_out, int out_size) {
    const float* k    = (const float*)d_in[0];
    const float* v    = (const float*)d_in[1];
    const float* q    = (const float*)d_in[2];
    const void*  mask = d_in[3];
    const float* sbias = (const float*)d_in[4];
    const float* Wq = (const float*)d_in[5];
    const float* bq = (const float*)d_in[6];
    const float* Wk = (const float*)d_in[7];
    const float* bk = (const float*)d_in[8];
    const float* Wv = (const float*)d_in[9];
    const float* bv = (const float*)d_in[10];
    const float* Wo = (const float*)d_in[11];
    const float* bo = (const float*)d_in[12];
    float* out = (float*)d_out;

    float *qp, *kp, *vp, *ctx;
    unsigned *ah, *al, *wh, *wl;
    cudaGetSymbolAddress((void**)&qp,  g_qp);
    cudaGetSymbolAddress((void**)&kp,  g_kp);
    cudaGetSymbolAddress((void**)&vp,  g_vp);
    cudaGetSymbolAddress((void**)&ctx, g_ctx);
    cudaGetSymbolAddress((void**)&ah,  g_act_h);
    cudaGetSymbolAddress((void**)&al,  g_act_l);
    cudaGetSymbolAddress((void**)&wh,  g_Wh);
    cudaGetSymbolAddress((void**)&wl,  g_Wl);

    const int WSZ = (HD/2)*HD;
    const int SMEM_G = (2*128*36 + 2*32*72) * 4;
    cudaFuncSetAttribute(gemm_bf16, cudaFuncAttributeMaxDynamicSharedMemorySize, SMEM_G);

    detect_mask_kernel<<<1, 1>>>(mask);
    bitpack_mask<<<(NS*NS)/256, 256>>>(mask);

    pack_w<<<512, 256>>>(Wq, wh + 0*WSZ, wl + 0*WSZ);
    pack_w<<<512, 256>>>(Wk, wh + 1*WSZ, wl + 1*WSZ);
    pack_w<<<512, 256>>>(Wv, wh + 2*WSZ, wl + 2*WSZ);
    pack_w<<<512, 256>>>(Wo, wh + 3*WSZ, wl + 3*WSZ);

    const int ACT_TOT = NB*NS*(HD/2);
    dim3 gb(8, 32);

    pack_act<<<ACT_TOT/256, 256>>>(q, ah, al, ACT_TOT);
    gemm_bf16<<<gb, 256, SMEM_G>>>(ah, al, wh + 0*WSZ, wl + 0*WSZ, bq, qp);
    pack_act<<<ACT_TOT/256, 256>>>(k, ah, al, ACT_TOT);
    gemm_bf16<<<gb, 256, SMEM_G>>>(ah, al, wh + 1*WSZ, wl + 1*WSZ, bk, kp);
    pack_act<<<ACT_TOT/256, 256>>>(v, ah, al, ACT_TOT);
    gemm_bf16<<<gb, 256, SMEM_G>>>(ah, al, wh + 2*WSZ, wl + 2*WSZ, bv, vp);

    dim3 ga(NS/128, NH);
    attn_fp16<<<ga, 256>>>(qp, kp, vp, sbias, ctx);

    pack_act<<<ACT_TOT/256, 256>>>(ctx, ah, al, ACT_TOT);
    gemm_bf16<<<gb, 256, SMEM_G>>>(ah, al, wh + 3*WSZ, wl + 3*WSZ, bo, out);
}